// round 4
// baseline (speedup 1.0000x reference)
#include <cuda_runtime.h>
#include <math.h>

#define N_PROP 1024
#define C_ALL 81
#define CF 80
#define DET 100
#define SCORE_THRESH 0.05f
#define NMS_THRESH 0.5f
#define IMG_W 1333.0f
#define IMG_H 800.0f
#define CAP 1024
#define KEEP_CAP 16384
#define SURV_CAP 2048

typedef unsigned long long ull;

// Scratch (allocation-free: __device__ globals; zero-initialized at load,
// and reset at end of each run so graph replays are deterministic).
__device__ ull    g_ckey[CF][CAP];
__device__ float4 g_cbox[CF][CAP];
__device__ int    g_ccnt[CF];
__device__ ull    g_keep_key[KEEP_CAP];
__device__ float4 g_keep_box[KEEP_CAP];
__device__ int    g_keep_count = 0;
__device__ int    g_done = 0;

// ---------------------------------------------------------------------------
// K0: warp per proposal. Softmax over 81 classes, then each lane evaluates
// its 3 classes; valid (prob>thresh) candidates are decoded, clipped, and
// scattered into per-class candidate lists.
// ---------------------------------------------------------------------------
__global__ void k0_prep(const float* __restrict__ logits,
                        const float* __restrict__ rel,
                        const float* __restrict__ props) {
    int warp = threadIdx.x >> 5, lane = threadIdx.x & 31;
    int n = blockIdx.x * 8 + warp;
    if (n >= N_PROP) return;

    const float* L = logits + n * C_ALL;
    float a = L[lane];
    float b = L[lane + 32];
    float c = (lane + 64 < C_ALL) ? L[lane + 64] : -1e30f;
    float mx = fmaxf(a, fmaxf(b, c));
    #pragma unroll
    for (int off = 16; off > 0; off >>= 1)
        mx = fmaxf(mx, __shfl_xor_sync(0xFFFFFFFFu, mx, off));
    float ea = expf(a - mx), eb = expf(b - mx);
    float ec = (lane + 64 < C_ALL) ? expf(c - mx) : 0.f;
    float s = ea + eb + ec;
    #pragma unroll
    for (int off = 16; off > 0; off >>= 1)
        s += __shfl_xor_sync(0xFFFFFFFFu, s, off);
    float rinv = 1.0f / s;

    // proposal geometry (warp-uniform, L1 broadcast)
    float4 p = ((const float4*)props)[n];
    float w = p.z - p.x + 1.0f, h = p.w - p.y + 1.0f;
    float cx = p.x + 0.5f * w, cy = p.y + 0.5f * h;

    const float CLIP = 4.135166556742356f;  // log(1000/16)
    #pragma unroll
    for (int q = 0; q < 3; ++q) {
        int cls = lane + 32 * q;
        if (cls < 1 || cls >= C_ALL) continue;
        float e = (q == 0) ? ea : (q == 1) ? eb : ec;
        float prob = e * rinv;
        if (prob > SCORE_THRESH) {
            int cf = cls - 1;
            float4 r4 = *(const float4*)(rel + n * (4 * C_ALL) + 4 * cls);
            float dx = r4.x * 0.1f;
            float dy = r4.y * 0.1f;
            float dw = fminf(r4.z * 0.2f, CLIP);
            float dh = fminf(r4.w * 0.2f, CLIP);
            float pcx = dx * w + cx, pcy = dy * h + cy;
            float pw = expf(dw) * w, ph = expf(dh) * h;
            float x1 = pcx - 0.5f * pw;
            float y1 = pcy - 0.5f * ph;
            float x2 = pcx + 0.5f * pw - 1.0f;
            float y2 = pcy + 0.5f * ph - 1.0f;
            x1 = fminf(fmaxf(x1, 0.f), IMG_W - 1.f);
            x2 = fminf(fmaxf(x2, 0.f), IMG_W - 1.f);
            y1 = fminf(fmaxf(y1, 0.f), IMG_H - 1.f);
            y2 = fminf(fmaxf(y2, 0.f), IMG_H - 1.f);
            int slot = atomicAdd(&g_ccnt[cf], 1);
            if (slot >= 0 && slot < CAP) {
                g_cbox[cf][slot] = make_float4(x1, y1, x2, y2);
                // key: [63:32]=scorebits, [19:10]=(1023-n) (idx asc ties), [9:0]=slot
                g_ckey[cf][slot] = ((ull)__float_as_uint(prob) << 32)
                                 | ((ull)(unsigned)(1023 - n) << 10)
                                 | (ull)(unsigned)slot;
            }
        }
    }
}

// ---------------------------------------------------------------------------
// K1: one warp (block of 32) per class. Sort + greedy NMS, warp-local only.
// The last block to finish also performs the global top-100 and emits output.
// ---------------------------------------------------------------------------
__global__ void k1_nms_topk(float* __restrict__ out) {
    int cf = blockIdx.x;
    int lane = threadIdx.x;

    __shared__ ull skey[CAP];       // reused as hist (int[2048]) in topk
    __shared__ float4 sbox[CAP];    // reused as survivor keys (ull[2048]) in topk
    __shared__ unsigned char ssupp[CAP];

    int c = g_ccnt[cf];
    if (c > CAP) c = CAP;

    if (c > 0) {
        for (int i = lane; i < c; i += 32) skey[i] = g_ckey[cf][i];
        int M = 32;
        while (M < c) M <<= 1;
        for (int i = c + lane; i < M; i += 32) skey[i] = 0ull;
        __syncwarp();

        // bitonic sort descending (warp-local)
        for (int k = 2; k <= M; k <<= 1) {
            for (int j = k >> 1; j > 0; j >>= 1) {
                for (int i = lane; i < M; i += 32) {
                    int ixj = i ^ j;
                    if (ixj > i) {
                        ull A = skey[i], B = skey[ixj];
                        bool up = ((i & k) == 0);
                        if (up ? (A < B) : (A > B)) { skey[i] = B; skey[ixj] = A; }
                    }
                }
                __syncwarp();
            }
        }

        for (int i = lane; i < c; i += 32) {
            sbox[i] = g_cbox[cf][skey[i] & 0x3FFu];
            ssupp[i] = 0;
        }
        __syncwarp();

        // greedy NMS (legacy +1 IoU, strict > threshold)
        for (int r = 0; r < c; ++r) {
            if (!ssupp[r]) {
                float4 pb = sbox[r];
                if (lane == 0) {
                    int slot = atomicAdd(&g_keep_count, 1);
                    if (slot >= 0 && slot < KEEP_CAP) {
                        unsigned flat = (unsigned)(cf * N_PROP + r);   // < 2^17
                        unsigned sb = (unsigned)(skey[r] >> 32);
                        // kept key: [63:32]=score, [31:15]=(0x1FFFF-flat), [14:0]=slot
                        g_keep_key[slot] = ((ull)sb << 32)
                                         | ((ull)(0x1FFFFu - flat) << 15)
                                         | (ull)(slot & 0x7FFF);
                        g_keep_box[slot] = pb;
                    }
                }
                float pa = (pb.z - pb.x + 1.f) * (pb.w - pb.y + 1.f);
                for (int j = r + 1 + lane; j < c; j += 32) {
                    if (!ssupp[j]) {
                        float4 q = sbox[j];
                        float qa = (q.z - q.x + 1.f) * (q.w - q.y + 1.f);
                        float ix1 = fmaxf(pb.x, q.x), iy1 = fmaxf(pb.y, q.y);
                        float ix2 = fminf(pb.z, q.z), iy2 = fminf(pb.w, q.w);
                        float iw = fmaxf(ix2 - ix1 + 1.f, 0.f);
                        float ih = fmaxf(iy2 - iy1 + 1.f, 0.f);
                        float inter = iw * ih;
                        if (inter > NMS_THRESH * (pa + qa - inter)) ssupp[j] = 1;
                    }
                }
            }
            __syncwarp();
        }
    }

    // reset per-class state for next graph replay
    if (lane == 0) g_ccnt[cf] = 0;

    // signal completion; last block to arrive performs the global top-k
    __threadfence();
    int t = 0;
    if (lane == 0) t = atomicAdd(&g_done, 1);
    t = __shfl_sync(0xFFFFFFFFu, t, 0);
    if (t != CF - 1) return;
    __threadfence();
    __syncwarp();

    // ---------------- top-100 (single warp) ----------------
    int* hist = (int*)skey;            // 2048 ints (8KB)
    ull* S = (ull*)sbox;               // 2048 ulls (16KB)
    __shared__ int s_cnt, s_bstar;

    int m = 0;
    if (lane == 0) m = atomicAdd(&g_keep_count, 0);   // coherent L2 read
    m = __shfl_sync(0xFFFFFFFFu, m, 0);
    if (m > KEEP_CAP) m = KEEP_CAP;

    for (int i = lane; i < 6 * DET; i += 32) out[i] = 0.f;
    for (int i = lane; i < 2048; i += 32) hist[i] = 0;
    if (lane == 0) { s_cnt = 0; s_bstar = 0; }
    __syncwarp();

    // 12-bit monotone bucket = top bits of key (sign=0, exp8, mant3)
    for (int i = lane; i < m; i += 32)
        atomicAdd(&hist[(unsigned)(__ldcg(&g_keep_key[i]) >> 52) & 0x7FFu], 1);
    __syncwarp();

    // find bucket of the DET-th largest key, scanning high->low
    {
        int base = lane * 64;
        int cs = 0;
        for (int j = 0; j < 64; ++j) cs += hist[base + j];
        int suf = cs;   // inclusive suffix over lanes >= lane
        #pragma unroll
        for (int off = 1; off < 32; off <<= 1) {
            int v = __shfl_down_sync(0xFFFFFFFFu, suf, off);
            if (lane + off < 32) suf += v;
        }
        int sufExcl = suf - cs;
        if (sufExcl < DET && suf >= DET) {
            int cum = sufExcl;
            for (int b = base + 63; b >= base; --b) {
                cum += hist[b];
                if (cum >= DET) { s_bstar = b; break; }
            }
        }
    }
    __syncwarp();
    unsigned bstar = (unsigned)s_bstar;

    // compact survivors (bucket >= b*)
    for (int i = lane; i < m; i += 32) {
        ull k = __ldcg(&g_keep_key[i]);
        if (((unsigned)(k >> 52) & 0x7FFu) >= bstar) {
            int p = atomicAdd(&s_cnt, 1);
            if (p >= 0 && p < SURV_CAP) S[p] = k;
        }
    }
    __syncwarp();
    int sc = s_cnt;
    if (sc > SURV_CAP) sc = SURV_CAP;

    // exact rank of each survivor (keys unique) == global rank
    for (int i = lane; i < sc; i += 32) {
        ull k = S[i];
        int rank = 0;
        for (int j = 0; j < sc; ++j) rank += (S[j] > k);
        if (rank < DET) {
            float score = __uint_as_float((unsigned)(k >> 32));
            unsigned flat = 0x1FFFFu - (unsigned)((k >> 15) & 0x1FFFFu);
            int slot = (int)(k & 0x7FFFu);
            if (slot >= KEEP_CAP) slot = 0;
            float4 b;
            b.x = __ldcg(&g_keep_box[slot].x);
            b.y = __ldcg(&g_keep_box[slot].y);
            b.z = __ldcg(&g_keep_box[slot].z);
            b.w = __ldcg(&g_keep_box[slot].w);
            out[rank * 4 + 0] = b.x;
            out[rank * 4 + 1] = b.y;
            out[rank * 4 + 2] = b.z;
            out[rank * 4 + 3] = b.w;
            out[4 * DET + rank] = score;
            out[5 * DET + rank] = (float)(flat / N_PROP + 1);
        }
    }

    // reset global state for next graph replay
    __syncwarp();
    if (lane == 0) { g_keep_count = 0; g_done = 0; }
}

extern "C" void kernel_launch(void* const* d_in, const int* in_sizes, int n_in,
                              void* d_out, int out_size) {
    const float* class_logits = (const float*)d_in[0];   // [1024, 81]
    const float* box_regression = (const float*)d_in[1]; // [1024, 324]
    const float* proposals = (const float*)d_in[2];      // [1024, 4]
    float* out = (float*)d_out;                          // 600 floats

    k0_prep<<<N_PROP / 8, 256>>>(class_logits, box_regression, proposals);
    k1_nms_topk<<<CF, 32>>>(out);
}

// round 5
// speedup vs baseline: 2.2023x; 2.2023x over previous
#include <cuda_runtime.h>
#include <math.h>

#define N_PROP 1024
#define C_ALL 81
#define CF 80
#define DET 100
#define SCORE_THRESH 0.05f
#define NMS_THRESH 0.5f
#define IMG_W 1333.0f
#define IMG_H 800.0f
#define CAP 1024
#define KEEP_CAP 16384
#define SURV_CAP 2048
#define FULL 0xFFFFFFFFu

typedef unsigned long long ull;

// Scratch (allocation-free __device__ globals; zero at load, reset each run).
__device__ ull    g_ckey[CF][CAP];
__device__ float4 g_cbox[CF][CAP];
__device__ int    g_ccnt[CF];
__device__ ull    g_keep_key[KEEP_CAP];
__device__ float4 g_keep_box[KEEP_CAP];
__device__ int    g_hist[2048];
__device__ int    g_keep_count = 0;
__device__ int    g_done = 0;

// ---------------------------------------------------------------------------
// K0: warp per proposal. Softmax over 81 classes; valid (prob>thresh)
// candidates decoded, clipped, scattered into per-class lists.
// ---------------------------------------------------------------------------
__global__ void k0_prep(const float* __restrict__ logits,
                        const float* __restrict__ rel,
                        const float* __restrict__ props) {
    int warp = threadIdx.x >> 5, lane = threadIdx.x & 31;
    int n = blockIdx.x * 8 + warp;
    if (n >= N_PROP) return;

    const float* L = logits + n * C_ALL;
    float a = L[lane];
    float b = L[lane + 32];
    float c = (lane + 64 < C_ALL) ? L[lane + 64] : -1e30f;
    float mx = fmaxf(a, fmaxf(b, c));
    #pragma unroll
    for (int off = 16; off > 0; off >>= 1)
        mx = fmaxf(mx, __shfl_xor_sync(FULL, mx, off));
    float ea = expf(a - mx), eb = expf(b - mx);
    float ec = (lane + 64 < C_ALL) ? expf(c - mx) : 0.f;
    float s = ea + eb + ec;
    #pragma unroll
    for (int off = 16; off > 0; off >>= 1)
        s += __shfl_xor_sync(FULL, s, off);
    float rinv = 1.0f / s;

    float4 p = ((const float4*)props)[n];
    float w = p.z - p.x + 1.0f, h = p.w - p.y + 1.0f;
    float cx = p.x + 0.5f * w, cy = p.y + 0.5f * h;

    const float CLIP = 4.135166556742356f;  // log(1000/16)
    #pragma unroll
    for (int q = 0; q < 3; ++q) {
        int cls = lane + 32 * q;
        if (cls < 1 || cls >= C_ALL) continue;
        float e = (q == 0) ? ea : (q == 1) ? eb : ec;
        float prob = e * rinv;
        if (prob > SCORE_THRESH) {
            int cf = cls - 1;
            float4 r4 = *(const float4*)(rel + n * (4 * C_ALL) + 4 * cls);
            float dx = r4.x * 0.1f;
            float dy = r4.y * 0.1f;
            float dw = fminf(r4.z * 0.2f, CLIP);
            float dh = fminf(r4.w * 0.2f, CLIP);
            float pcx = dx * w + cx, pcy = dy * h + cy;
            float pw = expf(dw) * w, ph = expf(dh) * h;
            float x1 = pcx - 0.5f * pw;
            float y1 = pcy - 0.5f * ph;
            float x2 = pcx + 0.5f * pw - 1.0f;
            float y2 = pcy + 0.5f * ph - 1.0f;
            x1 = fminf(fmaxf(x1, 0.f), IMG_W - 1.f);
            x2 = fminf(fmaxf(x2, 0.f), IMG_W - 1.f);
            y1 = fminf(fmaxf(y1, 0.f), IMG_H - 1.f);
            y2 = fminf(fmaxf(y2, 0.f), IMG_H - 1.f);
            int slot = atomicAdd(&g_ccnt[cf], 1);
            if (slot >= 0 && slot < CAP) {
                g_cbox[cf][slot] = make_float4(x1, y1, x2, y2);
                // key: [63:32]=scorebits, [19:10]=(1023-n) idx-asc ties, [9:0]=slot
                g_ckey[cf][slot] = ((ull)__float_as_uint(prob) << 32)
                                 | ((ull)(unsigned)(1023 - n) << 10)
                                 | (ull)(unsigned)slot;
            }
        }
    }
}

__device__ __forceinline__ void write_keep(int slot, int cf, int pos,
                                           ull srckey, float4 box) {
    if (slot < 0 || slot >= KEEP_CAP) return;
    unsigned flat = (unsigned)(cf * N_PROP + pos);          // < 2^17
    unsigned sb = (unsigned)(srckey >> 32);
    // kept key: [63:32]=score, [31:15]=(0x1FFFF-flat), [14:0]=slot
    ull kk = ((ull)sb << 32) | ((ull)(0x1FFFFu - flat) << 15)
           | (ull)(slot & 0x7FFF);
    g_keep_key[slot] = kk;
    g_keep_box[slot] = box;
    atomicAdd(&g_hist[(unsigned)(kk >> 52) & 0x7FFu], 1);
}

// ---------------------------------------------------------------------------
// K1: 80 blocks x 256. Warp 0 does per-class NMS (register fast path c<=64,
// shared fallback). Last block to arrive runs the top-100 with 256 threads.
// ---------------------------------------------------------------------------
__global__ void __launch_bounds__(256) k1_nms_topk(float* __restrict__ out) {
    int cf = blockIdx.x;
    int tid = threadIdx.x;
    int lane = tid & 31;
    int warp = tid >> 5;

    __shared__ ull skey[CAP];         // sort buffer (fallback); chunk sums in topk
    __shared__ float4 sbox[CAP];      // fallback boxes; survivor keys S[] in topk
    __shared__ unsigned char ssupp[CAP];
    __shared__ int s_last;

    int c = g_ccnt[cf];
    if (c > CAP) c = CAP;
    if (tid == 0) g_ccnt[cf] = 0;     // reset for next replay

    if (warp == 0 && c > 0) {
        // ---- sort keys descending in shared (warp 0 only) ----
        for (int i = lane; i < c; i += 32) skey[i] = g_ckey[cf][i];
        int M = 32;
        while (M < c) M <<= 1;
        for (int i = c + lane; i < M; i += 32) skey[i] = 0ull;
        __syncwarp();
        for (int k = 2; k <= M; k <<= 1) {
            for (int j = k >> 1; j > 0; j >>= 1) {
                for (int i = lane; i < M; i += 32) {
                    int ixj = i ^ j;
                    if (ixj > i) {
                        ull A = skey[i], B = skey[ixj];
                        bool up = ((i & k) == 0);
                        if (up ? (A < B) : (A > B)) { skey[i] = B; skey[ixj] = A; }
                    }
                }
                __syncwarp();
            }
        }

        if (c <= 64) {
            // ---- register NMS: lane owns sorted positions lane, lane+32 ----
            ull keyA = skey[lane];
            ull keyB = (c > 32) ? skey[lane + 32] : 0ull;
            float4 bA = make_float4(0, 0, 0, 1e9f), bB = make_float4(0, 0, 0, 1e9f);
            if (lane < c)      bA = g_cbox[cf][(int)(keyA & 0x3FFu)];
            if (lane + 32 < c) bB = g_cbox[cf][(int)(keyB & 0x3FFu)];
            float aA = (bA.z - bA.x + 1.f) * (bA.w - bA.y + 1.f);
            float aB = (bB.z - bB.x + 1.f) * (bB.w - bB.y + 1.f);

            unsigned rem0 = (c >= 32) ? FULL : ((1u << c) - 1u);
            unsigned rem1 = (c <= 32) ? 0u
                          : ((c >= 64) ? FULL : ((1u << (c - 32)) - 1u));
            unsigned keep0 = 0, keep1 = 0;

            while (rem0 | rem1) {
                bool in0 = (rem0 != 0);
                unsigned rm = in0 ? rem0 : rem1;
                int r = __ffs(rm) - 1;          // lowest index = highest score
                unsigned bit = 1u << r;
                if (in0) { rem0 &= ~bit; keep0 |= bit; }
                else     { rem1 &= ~bit; keep1 |= bit; }

                float lx1 = __shfl_sync(FULL, in0 ? bA.x : bB.x, r);
                float ly1 = __shfl_sync(FULL, in0 ? bA.y : bB.y, r);
                float lx2 = __shfl_sync(FULL, in0 ? bA.z : bB.z, r);
                float ly2 = __shfl_sync(FULL, in0 ? bA.w : bB.w, r);
                float la  = __shfl_sync(FULL, in0 ? aA : aB, r);

                float iwA = fminf(lx2, bA.z) - fmaxf(lx1, bA.x) + 1.f;
                float ihA = fminf(ly2, bA.w) - fmaxf(ly1, bA.y) + 1.f;
                float inA = fmaxf(iwA, 0.f) * fmaxf(ihA, 0.f);
                bool sA = inA > NMS_THRESH * (la + aA - inA);
                float iwB = fminf(lx2, bB.z) - fmaxf(lx1, bB.x) + 1.f;
                float ihB = fminf(ly2, bB.w) - fmaxf(ly1, bB.y) + 1.f;
                float inB = fmaxf(iwB, 0.f) * fmaxf(ihB, 0.f);
                bool sB = inB > NMS_THRESH * (la + aB - inB);

                unsigned m0 = __ballot_sync(FULL, sA);
                unsigned m1 = __ballot_sync(FULL, sB);
                int rp = in0 ? r : (r + 32);
                unsigned after0, after1;
                if (rp < 32) {
                    after0 = (rp == 31) ? 0u : (FULL << (rp + 1));
                    after1 = FULL;
                } else {
                    after0 = 0u;
                    after1 = (rp == 63) ? 0u : (FULL << (rp - 31));
                }
                rem0 &= ~(m0 & after0);
                rem1 &= ~(m1 & after1);
            }

            int kc = __popc(keep0) + __popc(keep1);
            int base = 0;
            if (lane == 0) base = atomicAdd(&g_keep_count, kc);
            base = __shfl_sync(FULL, base, 0);
            if ((keep0 >> lane) & 1u) {
                int rank = __popc(keep0 & ((1u << lane) - 1u));
                write_keep(base + rank, cf, lane, keyA, bA);
            }
            if ((keep1 >> lane) & 1u) {
                int rank = __popc(keep0) + __popc(keep1 & ((1u << lane) - 1u));
                write_keep(base + rank, cf, lane + 32, keyB, bB);
            }
        } else {
            // ---- shared fallback (rare: c > 64) ----
            for (int i = lane; i < c; i += 32) {
                sbox[i] = g_cbox[cf][(int)(skey[i] & 0x3FFu)];
                ssupp[i] = 0;
            }
            __syncwarp();
            for (int r = 0; r < c; ++r) {
                if (!ssupp[r]) {
                    float4 pb = sbox[r];
                    float pa = (pb.z - pb.x + 1.f) * (pb.w - pb.y + 1.f);
                    for (int j = r + 1 + lane; j < c; j += 32) {
                        if (!ssupp[j]) {
                            float4 q = sbox[j];
                            float qa = (q.z - q.x + 1.f) * (q.w - q.y + 1.f);
                            float iw = fminf(pb.z, q.z) - fmaxf(pb.x, q.x) + 1.f;
                            float ih = fminf(pb.w, q.w) - fmaxf(pb.y, q.y) + 1.f;
                            float inter = fmaxf(iw, 0.f) * fmaxf(ih, 0.f);
                            if (inter > NMS_THRESH * (pa + qa - inter)) ssupp[j] = 1;
                        }
                    }
                }
                __syncwarp();
            }
            // deferred write-out
            int total = 0;
            for (int b = 0; b < c; b += 32) {
                bool kept = (b + lane < c) && !ssupp[b + lane];
                total += __popc(__ballot_sync(FULL, kept));
            }
            int base = 0;
            if (lane == 0) base = atomicAdd(&g_keep_count, total);
            base = __shfl_sync(FULL, base, 0);
            int before = 0;
            for (int b = 0; b < c; b += 32) {
                bool kept = (b + lane < c) && !ssupp[b + lane];
                unsigned bal = __ballot_sync(FULL, kept);
                if (kept) {
                    int rank = before + __popc(bal & ((1u << lane) - 1u));
                    write_keep(base + rank, cf, b + lane, skey[b + lane], sbox[b + lane]);
                }
                before += __popc(bal);
            }
        }
    }

    // handshake: warp 0 publishes, last block runs topk with all 256 threads
    if (warp == 0) {
        __threadfence();
        int t = 0;
        if (lane == 0) {
            t = atomicAdd(&g_done, 1);
            s_last = (t == CF - 1);
        }
    }
    __syncthreads();
    if (!s_last) return;
    __threadfence();

    // ---------------- top-100 (256 threads) ----------------
    __shared__ int chunk[256];
    __shared__ int s_cnt, s_bstar, s_m;
    ull* S = (ull*)sbox;   // 2048 ulls

    if (tid == 0) {
        s_m = atomicAdd(&g_keep_count, 0);
        s_cnt = 0;
        s_bstar = 0;
    }
    for (int i = tid; i < 6 * DET; i += 256) out[i] = 0.f;
    __syncthreads();
    int m = s_m;
    if (m > KEEP_CAP) m = KEEP_CAP;

    // per-thread sum of 8 histogram buckets
    {
        int s = 0;
        #pragma unroll
        for (int j = 0; j < 8; ++j) s += g_hist[tid * 8 + j];
        chunk[tid] = s;
    }
    __syncthreads();

    // warp 0 finds bucket of the DET-th largest key (scan high -> low)
    if (warp == 0) {
        int g = 0;
        #pragma unroll
        for (int j = 0; j < 8; ++j) g += chunk[lane * 8 + j];
        int suf = g;      // inclusive suffix over lanes >= lane
        #pragma unroll
        for (int off = 1; off < 32; off <<= 1) {
            int v = __shfl_down_sync(FULL, suf, off);
            if (lane + off < 32) suf += v;
        }
        int sufExcl = suf - g;
        if (sufExcl < DET && suf >= DET) {
            // crossing group = lane; scan its 8 chunks high->low
            int cum = sufExcl;
            for (int t8 = lane * 8 + 7; t8 >= lane * 8; --t8) {
                int nc = cum + chunk[t8];
                if (nc >= DET) {
                    // crossing chunk t8; scan its 8 buckets high->low
                    for (int b = t8 * 8 + 7; b >= t8 * 8; --b) {
                        cum += g_hist[b];
                        if (cum >= DET) { s_bstar = b; break; }
                    }
                    break;
                }
                cum = nc;
            }
        }
    }
    __syncthreads();
    unsigned bstar = (unsigned)s_bstar;

    // compact survivors (bucket >= b*)
    for (int i = tid; i < m; i += 256) {
        ull k = __ldcg(&g_keep_key[i]);
        if (((unsigned)(k >> 52) & 0x7FFu) >= bstar) {
            int p = atomicAdd(&s_cnt, 1);
            if (p >= 0 && p < SURV_CAP) S[p] = k;
        }
    }
    __syncthreads();
    int sc = s_cnt;
    if (sc > SURV_CAP) sc = SURV_CAP;

    // exact rank of each survivor (keys unique) == global rank
    for (int i = tid; i < sc; i += 256) {
        ull k = S[i];
        int rank = 0;
        for (int j = 0; j < sc; ++j) rank += (S[j] > k);
        if (rank < DET) {
            float score = __uint_as_float((unsigned)(k >> 32));
            unsigned flat = 0x1FFFFu - (unsigned)((k >> 15) & 0x1FFFFu);
            int slot = (int)(k & 0x7FFFu);
            if (slot >= KEEP_CAP) slot = 0;
            float4 b;
            b.x = __ldcg(&g_keep_box[slot].x);
            b.y = __ldcg(&g_keep_box[slot].y);
            b.z = __ldcg(&g_keep_box[slot].z);
            b.w = __ldcg(&g_keep_box[slot].w);
            out[rank * 4 + 0] = b.x;
            out[rank * 4 + 1] = b.y;
            out[rank * 4 + 2] = b.z;
            out[rank * 4 + 3] = b.w;
            out[4 * DET + rank] = score;
            out[5 * DET + rank] = (float)(flat / N_PROP + 1);
        }
    }

    // reset global state for next graph replay
    __syncthreads();
    #pragma unroll
    for (int j = 0; j < 8; ++j) g_hist[tid * 8 + j] = 0;
    if (tid == 0) { g_keep_count = 0; g_done = 0; }
}

extern "C" void kernel_launch(void* const* d_in, const int* in_sizes, int n_in,
                              void* d_out, int out_size) {
    const float* class_logits = (const float*)d_in[0];   // [1024, 81]
    const float* box_regression = (const float*)d_in[1]; // [1024, 324]
    const float* proposals = (const float*)d_in[2];      // [1024, 4]
    float* out = (float*)d_out;                          // 600 floats

    k0_prep<<<N_PROP / 8, 256>>>(class_logits, box_regression, proposals);
    k1_nms_topk<<<CF, 256>>>(out);
}